// round 17
// baseline (speedup 1.0000x reference)
#include <cuda_runtime.h>
#include <cuda_bf16.h>
#include <cuda_fp16.h>
#include <math_constants.h>
#include <cstdint>

#define NQ        256
#define NK        50000
#define DD        64
#define KT        128
#define NKT       391          // ceil(50000/128)
#define NKPAD     (NKT * KT)   // 50048
#define GRID2     296          // 2 CTAs per SM, persistent over tiles
#define GRP       16           // candidate granularity (keys per group)
#define NHG       (NKT * 8)    // 3128 groups
#define OBS_ELEMS 3072
#define CAP       192
#define MARGIN    1.5f         // >> 2x f16-accum score error bound

// ---- static device scratch ----
__device__ __align__(16) __half g_kh[NKPAD * DD];   // pre-converted k (f16)
__device__ __align__(16) __half g_qh[NQ * DD];      // pre-converted q (f16)
__device__ __align__(16) float  g_ksq[NKPAD];       // ||k||^2 fp32 (INF pad)
__device__ __align__(16) float  g_hmin[NQ * NHG];
__device__ int g_topidx[NQ * 8];

// ---- score-kernel smem (bytes) ----
#define TSTRIDE_B  144
#define SM_Q     0             // 256 x 144 = 36864
#define SM_K0    36864         // 128 x 144 = 18432
#define SM_K1    55296         //           = 18432
#define SM_KSQ0  73728         // 512
#define SM_KSQ1  74240         // 512
#define SM_HST   74752         // 256 x 8 f32 = 8192
#define SM_TOTAL 82944

// ============================ helpers ============================
__device__ __forceinline__ uint32_t smem_u32(const void* p) {
    uint32_t a;
    asm("{ .reg .u64 t; cvta.to.shared.u64 t, %1; cvt.u32.u64 %0, t; }" : "=r"(a) : "l"(p));
    return a;
}
__device__ __forceinline__ void ldsm_x4(uint32_t& r0, uint32_t& r1, uint32_t& r2,
                                        uint32_t& r3, uint32_t a) {
    asm volatile("ldmatrix.sync.aligned.m8n8.x4.shared.b16 {%0,%1,%2,%3}, [%4];"
                 : "=r"(r0), "=r"(r1), "=r"(r2), "=r"(r3) : "r"(a));
}
// f16 x f16 -> f16 accumulate (D/C are 2 packed .f16x2 regs)
__device__ __forceinline__ void mma_f16acc(uint32_t& d0, uint32_t& d1,
                                           uint32_t a0, uint32_t a1, uint32_t a2, uint32_t a3,
                                           uint32_t b0, uint32_t b1) {
    asm volatile("mma.sync.aligned.m16n8k16.row.col.f16.f16.f16.f16 "
                 "{%0,%1},{%2,%3,%4,%5},{%6,%7},{%0,%1};"
                 : "+r"(d0), "+r"(d1)
                 : "r"(a0), "r"(a1), "r"(a2), "r"(a3), "r"(b0), "r"(b1));
}
__device__ __forceinline__ void cp_async16(uint32_t dst, const void* src) {
    asm volatile("cp.async.cg.shared.global [%0], [%1], 16;" :: "r"(dst), "l"(src));
}

// ======================================================================
// Kernel 0: one-time fp32 -> f16 conversion (k rows + ksq, q rows)
// grid 197 x 256: blocks 0..195 k (one row/thread), block 196 q.
// ======================================================================
__global__ __launch_bounds__(256) void knn_prep(
    const float* __restrict__ qm, const float* __restrict__ km)
{
    const int b = blockIdx.x, tid = threadIdx.x;
    if (b < 196) {
        const int row = b * 256 + tid;
        if (row >= NKPAD) return;
        uint4* dst = (uint4*)(g_kh + (size_t)row * DD);
        if (row < NK) {
            const float4* s = (const float4*)(km + (size_t)row * DD);
            float ss = 0.f;
            #pragma unroll
            for (int i = 0; i < 8; i++) {
                float4 v0 = s[i * 2], v1 = s[i * 2 + 1];
                ss = fmaf(v0.x, v0.x, ss); ss = fmaf(v0.y, v0.y, ss);
                ss = fmaf(v0.z, v0.z, ss); ss = fmaf(v0.w, v0.w, ss);
                ss = fmaf(v1.x, v1.x, ss); ss = fmaf(v1.y, v1.y, ss);
                ss = fmaf(v1.z, v1.z, ss); ss = fmaf(v1.w, v1.w, ss);
                __half2 a = __floats2half2_rn(v0.x, v0.y);
                __half2 c = __floats2half2_rn(v0.z, v0.w);
                __half2 e = __floats2half2_rn(v1.x, v1.y);
                __half2 f = __floats2half2_rn(v1.z, v1.w);
                uint4 u;
                u.x = *(uint32_t*)&a; u.y = *(uint32_t*)&c;
                u.z = *(uint32_t*)&e; u.w = *(uint32_t*)&f;
                dst[i] = u;
            }
            g_ksq[row] = ss;
        } else {
            uint4 z = make_uint4(0u, 0u, 0u, 0u);
            #pragma unroll
            for (int i = 0; i < 8; i++) dst[i] = z;
            g_ksq[row] = CUDART_INF_F;
        }
    } else {
        const int row = tid;   // 256 q rows
        const float4* s = (const float4*)(qm + (size_t)row * DD);
        uint4* dst = (uint4*)(g_qh + (size_t)row * DD);
        #pragma unroll
        for (int i = 0; i < 8; i++) {
            float4 v0 = s[i * 2], v1 = s[i * 2 + 1];
            __half2 a = __floats2half2_rn(v0.x, v0.y);
            __half2 c = __floats2half2_rn(v0.z, v0.w);
            __half2 e = __floats2half2_rn(v1.x, v1.y);
            __half2 f = __floats2half2_rn(v1.z, v1.w);
            uint4 u;
            u.x = *(uint32_t*)&a; u.y = *(uint32_t*)&c;
            u.z = *(uint32_t*)&e; u.w = *(uint32_t*)&f;
            dst[i] = u;
        }
    }
}

// ======================================================================
// Kernel 1: f16-accum mma GEMM -> per-(query,16-key-group) MIN
// grid 296, 256 threads (8 warps: 4 m-rows x 2 n-cols, 64x64 warp tiles)
// Each CTA: full 256q x one-or-two 128k tiles (c, c+296). 2 CTAs/SM.
// ======================================================================
__device__ __forceinline__ void load_ktile_async(uint32_t sb, int t, int buf, int tid) {
    const uint32_t kdst = sb + (buf ? SM_K1 : SM_K0);
    #pragma unroll
    for (int i = 0; i < 4; i++) {
        const int cid = tid + i * 256;            // 1024 chunks of 16B
        const int row = cid >> 3, part = cid & 7;
        const char* src = (const char*)(g_kh + (size_t)(t * KT + row) * DD) + part * 16;
        cp_async16(kdst + row * TSTRIDE_B + part * 16, src);
    }
    if (tid < 32)
        cp_async16(sb + (buf ? SM_KSQ1 : SM_KSQ0) + tid * 16,
                   (const char*)g_ksq + (size_t)(t * KT) * 4 + tid * 16);
}

__global__ __launch_bounds__(256, 2) void knn_score_min()
{
    extern __shared__ char smem[];
    const uint32_t sb = smem_u32(smem);
    const int tid  = threadIdx.x;
    const int wid  = tid >> 5;
    const int lane = tid & 31;
    const int c    = blockIdx.x;
    const int n_it = (c + GRID2 < NKT) ? 2 : 1;   // 95 CTAs do 2 tiles

    float* stage = (float*)(smem + SM_HST);

    // ---- prologue: async-load q tile + k tile c + ksq ----
    #pragma unroll
    for (int i = 0; i < 8; i++) {
        const int cid = tid + i * 256;            // 2048 chunks of 16B
        const int row = cid >> 3, part = cid & 7;
        const char* src = (const char*)(g_qh + (size_t)row * DD) + part * 16;
        cp_async16(sb + SM_Q + row * TSTRIDE_B + part * 16, src);
    }
    load_ktile_async(sb, c, 0, tid);
    asm volatile("cp.async.commit_group;" ::: "memory");
    asm volatile("cp.async.wait_group 0;" ::: "memory");
    __syncthreads();

    const int mrow = wid >> 1;          // 0..3 (64 rows each)
    const int ncol = wid & 1;           // 0..1 (64 cols each)
    int p = 0;

    for (int it = 0; it < n_it; it++) {
        const int t = c + it * GRID2;
        const bool have_next = (it + 1 < n_it);

        if (have_next) {
            load_ktile_async(sb, t + GRID2, 1 - p, tid);
            asm volatile("cp.async.commit_group;" ::: "memory");
        }

        // ---- GEMM from buffer p: 64x64 per warp, f16 accum ----
        const uint32_t kbase = sb + (p ? SM_K1 : SM_K0);
        const float* ksq = (const float*)(smem + (p ? SM_KSQ1 : SM_KSQ0));

        uint32_t acc[4][8][2];
        #pragma unroll
        for (int mt = 0; mt < 4; mt++)
            #pragma unroll
            for (int nt = 0; nt < 8; nt++) { acc[mt][nt][0] = 0u; acc[mt][nt][1] = 0u; }

        #pragma unroll
        for (int ks16 = 0; ks16 < 4; ks16++) {
            const uint32_t dby = ks16 * 32;
            uint32_t a[4][4];
            #pragma unroll
            for (int mt = 0; mt < 4; mt++) {
                uint32_t addr = sb + SM_Q
                    + (uint32_t)(mrow * 64 + mt * 16 + (lane & 15)) * TSTRIDE_B
                    + dby + ((lane >> 4) << 4);
                ldsm_x4(a[mt][0], a[mt][1], a[mt][2], a[mt][3], addr);
            }
            uint32_t b[8][2];
            #pragma unroll
            for (int np = 0; np < 4; np++) {
                uint32_t n = (uint32_t)(ncol * 64 + np * 16 + ((lane >> 4) << 3) + (lane & 7));
                uint32_t addr = kbase + n * TSTRIDE_B + dby + (((lane >> 3) & 1) << 4);
                ldsm_x4(b[np * 2][0], b[np * 2][1], b[np * 2 + 1][0], b[np * 2 + 1][1], addr);
            }
            #pragma unroll
            for (int mt = 0; mt < 4; mt++)
                #pragma unroll
                for (int nt = 0; nt < 8; nt++)
                    mma_f16acc(acc[mt][nt][0], acc[mt][nt][1],
                               a[mt][0], a[mt][1], a[mt][2], a[mt][3],
                               b[nt][0], b[nt][1]);
        }

        // ---- epilogue: per-(row, 16-col-group) min -> smem stage ----
        {
            const int g = lane >> 2, tq = lane & 3;
            #pragma unroll
            for (int mt = 0; mt < 4; mt++) {
                const int rowb = mrow * 64 + mt * 16 + g;
                #pragma unroll
                for (int gi = 0; gi < 4; gi++) {
                    float m0 = CUDART_INF_F, m1 = CUDART_INF_F;
                    #pragma unroll
                    for (int e = 0; e < 2; e++) {
                        const int nt = gi * 2 + e;
                        const int col = ncol * 64 + nt * 8 + tq * 2;
                        const float kq0 = ksq[col], kq1 = ksq[col + 1];
                        float2 lo = __half22float2(*(__half2*)&acc[mt][nt][0]);
                        float2 hi = __half22float2(*(__half2*)&acc[mt][nt][1]);
                        m0 = fminf(m0, fminf(fmaf(-2.f, lo.x, kq0),
                                             fmaf(-2.f, lo.y, kq1)));
                        m1 = fminf(m1, fminf(fmaf(-2.f, hi.x, kq0),
                                             fmaf(-2.f, hi.y, kq1)));
                    }
                    m0 = fminf(m0, __shfl_xor_sync(0xFFFFFFFFu, m0, 1));
                    m0 = fminf(m0, __shfl_xor_sync(0xFFFFFFFFu, m0, 2));
                    m1 = fminf(m1, __shfl_xor_sync(0xFFFFFFFFu, m1, 1));
                    m1 = fminf(m1, __shfl_xor_sync(0xFFFFFFFFu, m1, 2));
                    if (tq == 0) {
                        const int gg = ncol * 4 + gi;
                        stage[rowb * 8 + gg]       = m0;
                        stage[(rowb + 8) * 8 + gg] = m1;
                    }
                }
            }
        }
        __syncthreads();

        // ---- coalesced write-out: 256 threads x 2 float4 each ----
        {
            float4 v0 = *(float4*)&stage[tid * 8];
            float4 v1 = *(float4*)&stage[tid * 8 + 4];
            *(float4*)&g_hmin[(size_t)tid * NHG + t * 8]     = v0;
            *(float4*)&g_hmin[(size_t)tid * NHG + t * 8 + 4] = v1;
        }

        if (have_next) {
            asm volatile("cp.async.wait_group 0;" ::: "memory");
        }
        __syncthreads();
        p ^= 1;
    }
}

// ======================================================================
// Kernel 2: cutoff -> compact -> exact fp32 rescore -> exact top-8,
// shuffle-bitonic merges (round-16, CAP/MARGIN updated). grid NQ, 256 thr.
// ======================================================================
#define INS1(s_)                                                                 \
    if ((s_) < l[7]) {                                                           \
        l[7] = (s_);                                                             \
        _Pragma("unroll")                                                        \
        for (int u = 7; u > 0; u--)                                              \
            if (l[u] < l[u-1]) { float ts = l[u]; l[u] = l[u-1]; l[u-1] = ts; }  \
    }

__device__ __forceinline__ void wmerge8_f(float l[8], int off) {
    float b[8];
    #pragma unroll
    for (int i = 0; i < 8; i++) b[i] = __shfl_xor_sync(0xFFFFFFFFu, l[i], off);
    float t[8];
    #pragma unroll
    for (int i = 0; i < 8; i++) t[i] = fminf(l[i], b[7 - i]);
    #pragma unroll
    for (int d = 4; d >= 1; d >>= 1)
        #pragma unroll
        for (int i = 0; i < 8; i++)
            if ((i & d) == 0) {
                float mn = fminf(t[i], t[i + d]);
                float mx = fmaxf(t[i], t[i + d]);
                t[i] = mn; t[i + d] = mx;
            }
    #pragma unroll
    for (int i = 0; i < 8; i++) l[i] = t[i];
}

__device__ __forceinline__ void wmerge8_u64(unsigned long long l[8], int off) {
    unsigned long long b[8];
    #pragma unroll
    for (int i = 0; i < 8; i++) b[i] = __shfl_xor_sync(0xFFFFFFFFu, l[i], off);
    unsigned long long t[8];
    #pragma unroll
    for (int i = 0; i < 8; i++) t[i] = (l[i] < b[7 - i]) ? l[i] : b[7 - i];
    #pragma unroll
    for (int d = 4; d >= 1; d >>= 1)
        #pragma unroll
        for (int i = 0; i < 8; i++)
            if ((i & d) == 0) {
                unsigned long long mn = (t[i] < t[i + d]) ? t[i] : t[i + d];
                unsigned long long mx = (t[i] < t[i + d]) ? t[i + d] : t[i];
                t[i] = mn; t[i + d] = mx;
            }
    #pragma unroll
    for (int i = 0; i < 8; i++) l[i] = t[i];
}

__device__ __forceinline__ uint32_t fmono(float s) {
    uint32_t b = __float_as_uint(s);
    uint32_t mask = (uint32_t)(-(int32_t)(b >> 31)) | 0x80000000u;
    return b ^ mask;
}

__global__ __launch_bounds__(256) void knn_select(
    const float* __restrict__ qm, const float* __restrict__ km)
{
    __shared__ float qs[64];
    __shared__ float ws[8 * 8];
    __shared__ unsigned long long wq[8 * 8];
    __shared__ int   s_list[CAP];
    __shared__ int   s_cnt;
    __shared__ float s_cut;
    const int q = blockIdx.x, tid = threadIdx.x;
    const int wid = tid >> 5, lane = tid & 31;

    if (tid < 64) qs[tid] = qm[(size_t)q * DD + tid];
    if (tid == 0) s_cnt = 0;

    const float4* h4 = (const float4*)&g_hmin[(size_t)q * NHG];
    const int NV = NHG / 4;

    float l[8];
    #pragma unroll
    for (int i = 0; i < 8; i++) l[i] = CUDART_INF_F;
    #pragma unroll
    for (int r = 0; r < 4; r++) {
        const int v4 = tid + r * 256;
        if (v4 < NV) {
            float4 v = h4[v4];
            INS1(v.x); INS1(v.y); INS1(v.z); INS1(v.w);
        }
    }
    wmerge8_f(l, 16); wmerge8_f(l, 8); wmerge8_f(l, 4);
    wmerge8_f(l, 2);  wmerge8_f(l, 1);
    if (lane == 0) {
        #pragma unroll
        for (int i = 0; i < 8; i++) ws[wid * 8 + i] = l[i];
    }
    __syncthreads();
    if (wid == 0) {
        float m[8];
        #pragma unroll
        for (int i = 0; i < 8; i++)
            m[i] = (lane < 8) ? ws[lane * 8 + i] : CUDART_INF_F;
        wmerge8_f(m, 4); wmerge8_f(m, 2); wmerge8_f(m, 1);
        if (lane == 0) s_cut = m[7] + MARGIN;
    }
    __syncthreads();

    const float cut = s_cut;
    #pragma unroll
    for (int r = 0; r < 4; r++) {
        const int v4 = tid + r * 256;
        if (v4 < NV) {
            float4 v = h4[v4];
            if (v.x <= cut) { int p = atomicAdd(&s_cnt, 1); if (p < CAP) s_list[p] = v4 * 4; }
            if (v.y <= cut) { int p = atomicAdd(&s_cnt, 1); if (p < CAP) s_list[p] = v4 * 4 + 1; }
            if (v.z <= cut) { int p = atomicAdd(&s_cnt, 1); if (p < CAP) s_list[p] = v4 * 4 + 2; }
            if (v.w <= cut) { int p = atomicAdd(&s_cnt, 1); if (p < CAP) s_list[p] = v4 * 4 + 3; }
        }
    }
    __syncthreads();
    const int cnt = (s_cnt < CAP) ? s_cnt : CAP;

    unsigned long long kk[8];
    #pragma unroll
    for (int i = 0; i < 8; i++) kk[i] = 0xFFFFFFFFFFFFFFFFull;

    const float4* qp = (const float4*)qs;
    for (int u = tid; u < cnt * GRP; u += 256) {
        const int j = s_list[u >> 4] * GRP + (u & 15);
        if (j < NK) {
            const float4* kp = (const float4*)(km + (size_t)j * DD);
            float dot = 0.f, ks = 0.f;
            #pragma unroll
            for (int w = 0; w < 16; w++) {
                float4 kv = kp[w];
                float4 qv = qp[w];
                dot = fmaf(kv.x, qv.x, dot); ks = fmaf(kv.x, kv.x, ks);
                dot = fmaf(kv.y, qv.y, dot); ks = fmaf(kv.y, kv.y, ks);
                dot = fmaf(kv.z, qv.z, dot); ks = fmaf(kv.z, kv.z, ks);
                dot = fmaf(kv.w, qv.w, dot); ks = fmaf(kv.w, kv.w, ks);
            }
            float s = fmaf(-2.f, dot, ks);
            unsigned long long key = ((unsigned long long)fmono(s) << 32) | (uint32_t)j;
            if (key < kk[7]) {
                kk[7] = key;
                #pragma unroll
                for (int v = 7; v > 0; v--)
                    if (kk[v] < kk[v-1]) {
                        unsigned long long tv = kk[v]; kk[v] = kk[v-1]; kk[v-1] = tv;
                    }
            }
        }
    }
    wmerge8_u64(kk, 16); wmerge8_u64(kk, 8); wmerge8_u64(kk, 4);
    wmerge8_u64(kk, 2);  wmerge8_u64(kk, 1);
    if (lane == 0) {
        #pragma unroll
        for (int i = 0; i < 8; i++) wq[wid * 8 + i] = kk[i];
    }
    __syncthreads();
    if (wid == 0) {
        unsigned long long m[8];
        #pragma unroll
        for (int i = 0; i < 8; i++)
            m[i] = (lane < 8) ? wq[lane * 8 + i] : 0xFFFFFFFFFFFFFFFFull;
        wmerge8_u64(m, 4); wmerge8_u64(m, 2); wmerge8_u64(m, 1);
        if (lane == 0) {
            #pragma unroll
            for (int i = 0; i < 8; i++)
                g_topidx[q * 8 + i] = (int)(uint32_t)(m[i] & 0xFFFFFFFFull);
        }
    }
}

// ======================================================================
// Kernel 3: gather obs[idx] -> out [8, 256, 3072]  (2048 blocks, max MLP)
// ======================================================================
__global__ __launch_bounds__(256) void knn_gather_kernel(
    const float* __restrict__ obs, float* __restrict__ out)
{
    const int b  = blockIdx.x;
    const int kk = b >> 8;
    const int q  = b & 255;
    const int src = g_topidx[q * 8 + kk];

    const float4* s = (const float4*)(obs + (size_t)src * OBS_ELEMS);
    float4*       d = (float4*)(out + ((size_t)kk * NQ + q) * OBS_ELEMS);

    #pragma unroll
    for (int i = threadIdx.x; i < OBS_ELEMS / 4; i += 256)
        d[i] = s[i];
}

// ======================================================================
extern "C" void kernel_launch(void* const* d_in, const int* in_sizes, int n_in,
                              void* d_out, int out_size)
{
    const float* q   = (const float*)d_in[0];
    const float* k   = (const float*)d_in[1];
    const float* obs = (const float*)d_in[2];
    float* out = (float*)d_out;

    cudaFuncSetAttribute(knn_score_min,
                         cudaFuncAttributeMaxDynamicSharedMemorySize, SM_TOTAL);

    knn_prep<<<197, 256>>>(q, k);
    knn_score_min<<<GRID2, 256, SM_TOTAL>>>();
    knn_select<<<NQ, 256>>>(q, k);
    knn_gather_kernel<<<NQ * 8, 256>>>(obs, out);
}